// round 1
// baseline (speedup 1.0000x reference)
#include <cuda_runtime.h>
#include <math.h>

#define Nn 50000
#define Ee 800000
#define Dd 96
#define Ll 4
#define HID 128
#define OUTD 8

// ---------------- scratch (device globals; no allocs allowed) ----------------
__device__ float g_h[Nn * Dd];
__device__ float g_e[(size_t)Ee * Dd];
__device__ float g_enew[(size_t)Ee * Dd];
__device__ float g_Ah[Nn * Dd];
__device__ float g_Bh[Nn * Dd];
__device__ float g_Dh[Nn * Dd];
__device__ float g_Eh[Nn * Dd];
__device__ float g_num[Nn * Dd];
__device__ float g_den[Nn * Dd];
__device__ float g_hnew[Nn * Dd];
__device__ float g_hsum[Dd], g_hsq[Dd], g_esum[Dd], g_esq[Dd];
__device__ float g_hmu[Dd], g_hrstd[Dd], g_emu[Dd], g_erstd[Dd];

// ---------------- zero the per-layer accumulators ----------------
__global__ void zero_aggr()
{
    int idx = blockIdx.x * blockDim.x + threadIdx.x;   // grid covers Nn*Dd exactly
    g_num[idx] = 0.f;
    g_den[idx] = 0.f;
    if (idx < Dd) {
        g_hsum[idx] = 0.f; g_hsq[idx] = 0.f;
        g_esum[idx] = 0.f; g_esq[idx] = 0.f;
    }
}

// ---------------- input embeddings ----------------
// h = concat(h1[6], h2[4], z[16]) @ Wh[26,96] + bh
__global__ void embed_h(const float* __restrict__ h1, const float* __restrict__ h2,
                        const float* __restrict__ z,  const float* __restrict__ W,
                        const float* __restrict__ b)
{
    __shared__ float Ws[26 * Dd];
    int d = threadIdx.x;                 // 0..95
    for (int i = d; i < 26 * Dd; i += Dd) Ws[i] = W[i];
    float bias = b[d];
    int row0 = blockIdx.x * 64;
    __syncthreads();
    for (int i = 0; i < 64; i++) {
        int r = row0 + i;
        if (r >= Nn) break;
        float acc = bias;
        #pragma unroll
        for (int k = 0; k < 6; k++)  acc += h1[r * 6 + k]  * Ws[k * Dd + d];
        #pragma unroll
        for (int k = 0; k < 4; k++)  acc += h2[r * 4 + k]  * Ws[(6 + k) * Dd + d];
        #pragma unroll
        for (int k = 0; k < 16; k++) acc += z[r * 16 + k]  * Ws[(10 + k) * Dd + d];
        g_h[r * Dd + d] = acc;
    }
}

// e = efeat[E,4] @ We[4,96] + be
__global__ void embed_e(const float* __restrict__ ef, const float* __restrict__ W,
                        const float* __restrict__ b)
{
    __shared__ float Ws[4 * Dd];
    int d = threadIdx.x;
    for (int i = d; i < 4 * Dd; i += Dd) Ws[i] = W[i];
    float bias = b[d];
    int e0 = blockIdx.x * 128;
    __syncthreads();
    for (int i = 0; i < 128; i++) {
        int ed = e0 + i;
        float acc = bias;
        #pragma unroll
        for (int k = 0; k < 4; k++) acc += ef[ed * 4 + k] * Ws[k * Dd + d];
        g_e[(size_t)ed * Dd + d] = acc;
    }
}

// ---------------- generic [M,96] @ [96,96] + b GEMM ----------------
// block = 96 threads (thread d = output column), 64 rows/block, 8-row register tile.
__global__ void gemm96(const float* __restrict__ in, const float* __restrict__ W,
                       const float* __restrict__ b, float* __restrict__ out, int M)
{
    __shared__ float Ws[Dd * Dd];
    __shared__ float xs[8 * Dd];
    int d = threadIdx.x;
    for (int i = d; i < Dd * Dd; i += Dd) Ws[i] = W[i];
    float bias = b[d];
    int row0 = blockIdx.x * 64;
    for (int c = 0; c < 64; c += 8) {
        int r0 = row0 + c;
        __syncthreads();
        for (int t = d; t < 8 * Dd; t += Dd)
            xs[t] = (r0 + t / Dd < M) ? in[(size_t)r0 * Dd + t] : 0.f;
        __syncthreads();
        float acc[8];
        #pragma unroll
        for (int i = 0; i < 8; i++) acc[i] = 0.f;
        #pragma unroll 4
        for (int kk = 0; kk < Dd; kk += 4) {
            float w0 = Ws[kk * Dd + d];
            float w1 = Ws[(kk + 1) * Dd + d];
            float w2 = Ws[(kk + 2) * Dd + d];
            float w3 = Ws[(kk + 3) * Dd + d];
            #pragma unroll
            for (int i = 0; i < 8; i++) {
                float4 x = *(const float4*)&xs[i * Dd + kk];
                acc[i] += x.x * w0; acc[i] += x.y * w1;
                acc[i] += x.z * w2; acc[i] += x.w * w3;
            }
        }
        #pragma unroll
        for (int i = 0; i < 8; i++) {
            int r = r0 + i;
            if (r < M) out[(size_t)r * Dd + d] = acc[i] + bias;
        }
    }
}

// ---------------- fused edge pass ----------------
// e_new = e@WC + bC + Dh[src] + Eh[dst]; sig = sigmoid(e_new)
// atomically: num[dst] += sig*Bh[src]; den[dst] += sig; BN-stat partials for e_new.
__global__ void edge_fwd(const float* __restrict__ WC, const float* __restrict__ bC,
                         const int* __restrict__ src, const int* __restrict__ dst)
{
    __shared__ float Ws[Dd * Dd];
    __shared__ float xs[8 * Dd];
    __shared__ int ssrc[8], sdst[8];
    int d = threadIdx.x;
    for (int i = d; i < Dd * Dd; i += Dd) Ws[i] = WC[i];
    float bias = bC[d];
    float lsum = 0.f, lsq = 0.f;
    int e0 = blockIdx.x * 64;                        // Ee % 64 == 0
    for (int c = 0; c < 64; c += 8) {
        int base = e0 + c;
        __syncthreads();
        if (d < 8) { ssrc[d] = src[base + d]; sdst[d] = dst[base + d]; }
        const float* eptr = g_e + (size_t)base * Dd;
        for (int t = d; t < 8 * Dd; t += Dd) xs[t] = eptr[t];
        __syncthreads();
        float acc[8];
        #pragma unroll
        for (int i = 0; i < 8; i++) acc[i] = 0.f;
        #pragma unroll 4
        for (int kk = 0; kk < Dd; kk += 4) {
            float w0 = Ws[kk * Dd + d];
            float w1 = Ws[(kk + 1) * Dd + d];
            float w2 = Ws[(kk + 2) * Dd + d];
            float w3 = Ws[(kk + 3) * Dd + d];
            #pragma unroll
            for (int i = 0; i < 8; i++) {
                float4 x = *(const float4*)&xs[i * Dd + kk];
                acc[i] += x.x * w0; acc[i] += x.y * w1;
                acc[i] += x.z * w2; acc[i] += x.w * w3;
            }
        }
        #pragma unroll
        for (int i = 0; i < 8; i++) {
            int s = ssrc[i], t = sdst[i];
            float v = acc[i] + bias + g_Dh[s * Dd + d] + g_Eh[t * Dd + d];
            float sg = 1.f / (1.f + expf(-v));
            g_enew[(size_t)(base + i) * Dd + d] = v;
            atomicAdd(&g_num[t * Dd + d], sg * g_Bh[s * Dd + d]);
            atomicAdd(&g_den[t * Dd + d], sg);
            lsum += v; lsq += v * v;
        }
    }
    atomicAdd(&g_esum[d], lsum);
    atomicAdd(&g_esq[d], lsq);
}

// ---------------- h_new = Ah + num/(den+eps), + BN-stat partials ----------------
__global__ void hnew_stats()
{
    int d = threadIdx.x;
    int row0 = blockIdx.x * 64;
    float lsum = 0.f, lsq = 0.f;
    for (int i = 0; i < 64; i++) {
        int r = row0 + i;
        if (r >= Nn) break;
        int idx = r * Dd + d;
        float v = g_Ah[idx] + g_num[idx] / (g_den[idx] + 1e-6f);
        g_hnew[idx] = v;
        lsum += v; lsq += v * v;
    }
    atomicAdd(&g_hsum[d], lsum);
    atomicAdd(&g_hsq[d], lsq);
}

__global__ void finalize_stats()
{
    int d = threadIdx.x;
    float mu = g_hsum[d] / (float)Nn;
    float var = g_hsq[d] / (float)Nn - mu * mu;
    g_hmu[d] = mu; g_hrstd[d] = rsqrtf(var + 1e-5f);
    float mue = g_esum[d] / (float)Ee;
    float vare = g_esq[d] / (float)Ee - mue * mue;
    g_emu[d] = mue; g_erstd[d] = rsqrtf(vare + 1e-5f);
}

__global__ void apply_h(const float* __restrict__ g, const float* __restrict__ b)
{
    int idx = blockIdx.x * blockDim.x + threadIdx.x;   // exact grid: Nn*Dd
    int d = idx % Dd;
    float v = (g_hnew[idx] - g_hmu[d]) * g_hrstd[d] * g[d] + b[d];
    g_h[idx] += fmaxf(v, 0.f);
}

__global__ void apply_e(const float* __restrict__ g, const float* __restrict__ b)
{
    unsigned int idx = blockIdx.x * blockDim.x + threadIdx.x;  // exact grid: Ee*Dd
    int d = idx % Dd;
    float v = (g_enew[idx] - g_emu[d]) * g_erstd[d] * g[d] + b[d];
    g_e[idx] += fmaxf(v, 0.f);
}

// ---------------- MLP head: relu(h@W1+b1)@W2+b2, tanh, scale ----------------
__global__ void head_kernel(const float* __restrict__ W1, const float* __restrict__ b1,
                            const float* __restrict__ W2, const float* __restrict__ b2,
                            const float* __restrict__ max_action, float* __restrict__ out)
{
    extern __shared__ float sm[];
    float* W1s = sm;                       // 96*128
    float* W2s = W1s + Dd * HID;           // 128*8
    float* hs  = W2s + HID * OUTD;         // 96
    float* hid = hs + Dd;                  // 128
    int t = threadIdx.x;                   // 128
    for (int i = t; i < Dd * HID; i += HID) W1s[i] = W1[i];
    for (int i = t; i < HID * OUTD; i += HID) W2s[i] = W2[i];
    __syncthreads();
    int n0 = blockIdx.x * 32;
    for (int i = 0; i < 32; i++) {
        int n = n0 + i;
        if (n >= Nn) break;
        __syncthreads();
        if (t < Dd) hs[t] = g_h[n * Dd + t];
        __syncthreads();
        float acc = b1[t];
        #pragma unroll 4
        for (int k = 0; k < Dd; k++) acc += hs[k] * W1s[k * HID + t];
        hid[t] = fmaxf(acc, 0.f);
        __syncthreads();
        if (t < OUTD) {
            float o = b2[t];
            #pragma unroll 4
            for (int j = 0; j < HID; j++) o += hid[j] * W2s[j * OUTD + t];
            out[n * OUTD + t] = max_action[n] * tanhf(o);
        }
    }
}

// ---------------- launch ----------------
extern "C" void kernel_launch(void* const* d_in, const int* in_sizes, int n_in,
                              void* d_out, int out_size)
{
    const float* h1   = (const float*)d_in[0];
    const float* h2   = (const float*)d_in[1];
    const float* z    = (const float*)d_in[2];
    const float* ef   = (const float*)d_in[3];
    const float* max_action = (const float*)d_in[4];
    const float* Wh   = (const float*)d_in[5];
    const float* bh   = (const float*)d_in[6];
    const float* We   = (const float*)d_in[7];
    const float* be   = (const float*)d_in[8];
    const float* WA   = (const float*)d_in[9];
    const float* bA   = (const float*)d_in[10];
    const float* WB   = (const float*)d_in[11];
    const float* bB   = (const float*)d_in[12];
    const float* WC   = (const float*)d_in[13];
    const float* bC   = (const float*)d_in[14];
    const float* WD   = (const float*)d_in[15];
    const float* bD   = (const float*)d_in[16];
    const float* WE   = (const float*)d_in[17];
    const float* bE   = (const float*)d_in[18];
    const float* bn_h_g = (const float*)d_in[19];
    const float* bn_h_b = (const float*)d_in[20];
    const float* bn_e_g = (const float*)d_in[21];
    const float* bn_e_b = (const float*)d_in[22];
    const float* W1   = (const float*)d_in[23];
    const float* b1   = (const float*)d_in[24];
    const float* W2   = (const float*)d_in[25];
    const float* b2   = (const float*)d_in[26];
    const int*   src  = (const int*)d_in[27];
    const int*   dst  = (const int*)d_in[28];
    float* out = (float*)d_out;

    const int head_smem = (Dd * HID + HID * OUTD + Dd + HID) * (int)sizeof(float);
    cudaFuncSetAttribute(head_kernel, cudaFuncAttributeMaxDynamicSharedMemorySize, head_smem);

    float *ph, *pAh, *pBh, *pDh, *pEh;
    cudaGetSymbolAddress((void**)&ph,  g_h);
    cudaGetSymbolAddress((void**)&pAh, g_Ah);
    cudaGetSymbolAddress((void**)&pBh, g_Bh);
    cudaGetSymbolAddress((void**)&pDh, g_Dh);
    cudaGetSymbolAddress((void**)&pEh, g_Eh);

    const int node_blocks = (Nn + 63) / 64;      // 782

    embed_h<<<node_blocks, Dd>>>(h1, h2, z, Wh, bh);
    embed_e<<<Ee / 128, Dd>>>(ef, We, be);

    for (int l = 0; l < Ll; l++) {
        zero_aggr<<<(Nn * Dd) / 256, 256>>>();
        gemm96<<<node_blocks, Dd>>>(ph, WA + l * Dd * Dd, bA + l * Dd, pAh, Nn);
        gemm96<<<node_blocks, Dd>>>(ph, WB + l * Dd * Dd, bB + l * Dd, pBh, Nn);
        gemm96<<<node_blocks, Dd>>>(ph, WD + l * Dd * Dd, bD + l * Dd, pDh, Nn);
        gemm96<<<node_blocks, Dd>>>(ph, WE + l * Dd * Dd, bE + l * Dd, pEh, Nn);
        edge_fwd<<<Ee / 64, Dd>>>(WC + l * Dd * Dd, bC + l * Dd, src, dst);
        hnew_stats<<<node_blocks, Dd>>>();
        finalize_stats<<<1, Dd>>>();
        apply_h<<<(Nn * Dd) / 256, 256>>>(bn_h_g + l * Dd, bn_h_b + l * Dd);
        apply_e<<<(int)(((size_t)Ee * Dd) / 256), 256>>>(bn_e_g + l * Dd, bn_e_b + l * Dd);
    }

    head_kernel<<<(Nn + 31) / 32, HID, head_smem>>>(W1, b1, W2, b2, max_action, out);
}

// round 2
// speedup vs baseline: 1.1510x; 1.1510x over previous
#include <cuda_runtime.h>
#include <math.h>

#define Nn 50000
#define Ee 800000
#define Dd 96
#define Ll 4
#define HID 128
#define OUTD 8

// ---------------- scratch (device globals; no allocs allowed) ----------------
__device__ float g_h[Nn * Dd];
__device__ float g_e[(size_t)Ee * Dd];
__device__ float g_enew[(size_t)Ee * Dd];
__device__ float g_Ah[Nn * Dd];
__device__ float g_Bh[Nn * Dd];
__device__ float g_Dh[Nn * Dd];
__device__ float g_Eh[Nn * Dd];
__device__ float g_num[Nn * Dd];
__device__ float g_den[Nn * Dd];
__device__ float g_hnew[Nn * Dd];
__device__ float g_hsum[Dd], g_hsq[Dd], g_esum[Dd], g_esq[Dd];
__device__ float g_hmu[Dd], g_hrstd[Dd], g_emu[Dd], g_erstd[Dd];

// ---------------- zero the per-layer accumulators ----------------
__global__ void zero_aggr()
{
    int idx = blockIdx.x * blockDim.x + threadIdx.x;   // grid covers Nn*Dd exactly
    g_num[idx] = 0.f;
    g_den[idx] = 0.f;
    if (idx < Dd) {
        g_hsum[idx] = 0.f; g_hsq[idx] = 0.f;
        g_esum[idx] = 0.f; g_esq[idx] = 0.f;
    }
}

// ---------------- input embeddings ----------------
__global__ void embed_h(const float* __restrict__ h1, const float* __restrict__ h2,
                        const float* __restrict__ z,  const float* __restrict__ W,
                        const float* __restrict__ b)
{
    __shared__ float Ws[26 * Dd];
    int d = threadIdx.x;                 // 0..95
    int y = threadIdx.y;                 // 0..3
    int tid = y * Dd + d;
    for (int i = tid; i < 26 * Dd; i += 4 * Dd) Ws[i] = W[i];
    float bias = b[d];
    int row0 = blockIdx.x * 64 + y * 16;
    __syncthreads();
    for (int i = 0; i < 16; i++) {
        int r = row0 + i;
        if (r >= Nn) break;
        float acc = bias;
        #pragma unroll
        for (int k = 0; k < 6; k++)  acc += h1[r * 6 + k]  * Ws[k * Dd + d];
        #pragma unroll
        for (int k = 0; k < 4; k++)  acc += h2[r * 4 + k]  * Ws[(6 + k) * Dd + d];
        #pragma unroll
        for (int k = 0; k < 16; k++) acc += z[r * 16 + k]  * Ws[(10 + k) * Dd + d];
        g_h[r * Dd + d] = acc;
    }
}

__global__ void embed_e(const float* __restrict__ ef, const float* __restrict__ W,
                        const float* __restrict__ b)
{
    __shared__ float Ws[4 * Dd];
    int d = threadIdx.x;
    int y = threadIdx.y;
    int tid = y * Dd + d;
    for (int i = tid; i < 4 * Dd; i += 4 * Dd) Ws[i] = W[i];
    float bias = b[d];
    int e0 = blockIdx.x * 128 + y * 32;
    __syncthreads();
    for (int i = 0; i < 32; i++) {
        int ed = e0 + i;
        float acc = bias;
        #pragma unroll
        for (int k = 0; k < 4; k++) acc += ef[ed * 4 + k] * Ws[k * Dd + d];
        g_e[(size_t)ed * Dd + d] = acc;
    }
}

// ---------------- [M,96] @ [96,96] + b GEMM, 4 row-groups / block ----------------
__global__ void gemm96(const float* __restrict__ in, const float* __restrict__ W,
                       const float* __restrict__ b, float* __restrict__ out, int M)
{
    __shared__ float Ws[Dd * Dd];
    __shared__ float xs[4][8 * Dd];
    int d = threadIdx.x;          // output column
    int y = threadIdx.y;          // row group
    int tid = y * Dd + d;
    {
        const float4* W4 = (const float4*)W;
        float4* Ws4 = (float4*)Ws;
        for (int i = tid; i < Dd * Dd / 4; i += 4 * Dd) Ws4[i] = W4[i];
    }
    float bias = b[d];
    int row0 = blockIdx.x * 64 + y * 16;
    for (int c = 0; c < 16; c += 8) {
        int r0 = row0 + c;
        __syncthreads();
        {
            const float4* in4 = (const float4*)(in + (size_t)r0 * Dd);
            float4* xs4 = (float4*)xs[y];
            for (int t = d; t < 8 * Dd / 4; t += Dd) {
                int r = r0 + t / 24;
                xs4[t] = (r < M) ? in4[t] : make_float4(0.f, 0.f, 0.f, 0.f);
            }
        }
        __syncthreads();
        float acc[8];
        #pragma unroll
        for (int i = 0; i < 8; i++) acc[i] = 0.f;
        #pragma unroll 4
        for (int kk = 0; kk < Dd; kk += 4) {
            float w0 = Ws[kk * Dd + d];
            float w1 = Ws[(kk + 1) * Dd + d];
            float w2 = Ws[(kk + 2) * Dd + d];
            float w3 = Ws[(kk + 3) * Dd + d];
            #pragma unroll
            for (int i = 0; i < 8; i++) {
                float4 x = *(const float4*)&xs[y][i * Dd + kk];
                acc[i] += x.x * w0; acc[i] += x.y * w1;
                acc[i] += x.z * w2; acc[i] += x.w * w3;
            }
        }
        #pragma unroll
        for (int i = 0; i < 8; i++) {
            int r = r0 + i;
            if (r < M) out[(size_t)r * Dd + d] = acc[i] + bias;
        }
    }
}

// ---------------- fused edge pass ----------------
__global__ void edge_fwd(const float* __restrict__ WC, const float* __restrict__ bC,
                         const int* __restrict__ src, const int* __restrict__ dst)
{
    __shared__ float Ws[Dd * Dd];
    __shared__ float xs[4][8 * Dd];
    __shared__ int ssrc[4][8], sdst[4][8];
    int d = threadIdx.x;
    int y = threadIdx.y;
    int tid = y * Dd + d;
    {
        const float4* W4 = (const float4*)WC;
        float4* Ws4 = (float4*)Ws;
        for (int i = tid; i < Dd * Dd / 4; i += 4 * Dd) Ws4[i] = W4[i];
    }
    float bias = bC[d];
    float lsum = 0.f, lsq = 0.f;
    int e0 = blockIdx.x * 64 + y * 16;              // Ee % 64 == 0
    for (int c = 0; c < 16; c += 8) {
        int base = e0 + c;
        __syncthreads();
        if (d < 8) { ssrc[y][d] = src[base + d]; sdst[y][d] = dst[base + d]; }
        {
            const float4* ep4 = (const float4*)(g_e + (size_t)base * Dd);
            float4* xs4 = (float4*)xs[y];
            for (int t = d; t < 8 * Dd / 4; t += Dd) xs4[t] = ep4[t];
        }
        __syncthreads();
        float acc[8];
        #pragma unroll
        for (int i = 0; i < 8; i++) acc[i] = 0.f;
        #pragma unroll 4
        for (int kk = 0; kk < Dd; kk += 4) {
            float w0 = Ws[kk * Dd + d];
            float w1 = Ws[(kk + 1) * Dd + d];
            float w2 = Ws[(kk + 2) * Dd + d];
            float w3 = Ws[(kk + 3) * Dd + d];
            #pragma unroll
            for (int i = 0; i < 8; i++) {
                float4 x = *(const float4*)&xs[y][i * Dd + kk];
                acc[i] += x.x * w0; acc[i] += x.y * w1;
                acc[i] += x.z * w2; acc[i] += x.w * w3;
            }
        }
        #pragma unroll
        for (int i = 0; i < 8; i++) {
            int s = ssrc[y][i], t = sdst[y][i];
            float v = acc[i] + bias + g_Dh[s * Dd + d] + g_Eh[t * Dd + d];
            float sg = __frcp_rn(1.f + __expf(-v));
            g_enew[(size_t)(base + i) * Dd + d] = v;
            atomicAdd(&g_num[t * Dd + d], sg * g_Bh[s * Dd + d]);
            atomicAdd(&g_den[t * Dd + d], sg);
            lsum += v; lsq += v * v;
        }
    }
    atomicAdd(&g_esum[d], lsum);
    atomicAdd(&g_esq[d], lsq);
}

// ---------------- h_new = Ah + num/(den+eps), + BN-stat partials ----------------
__global__ void hnew_stats()
{
    int d = threadIdx.x;
    int y = threadIdx.y;
    int row0 = blockIdx.x * 64 + y * 16;
    float lsum = 0.f, lsq = 0.f;
    for (int i = 0; i < 16; i++) {
        int r = row0 + i;
        if (r >= Nn) break;
        int idx = r * Dd + d;
        float v = g_Ah[idx] + __fdividef(g_num[idx], g_den[idx] + 1e-6f);
        g_hnew[idx] = v;
        lsum += v; lsq += v * v;
    }
    atomicAdd(&g_hsum[d], lsum);
    atomicAdd(&g_hsq[d], lsq);
}

__global__ void finalize_stats()
{
    int d = threadIdx.x;
    float mu = g_hsum[d] / (float)Nn;
    float var = g_hsq[d] / (float)Nn - mu * mu;
    g_hmu[d] = mu; g_hrstd[d] = rsqrtf(var + 1e-5f);
    float mue = g_esum[d] / (float)Ee;
    float vare = g_esq[d] / (float)Ee - mue * mue;
    g_emu[d] = mue; g_erstd[d] = rsqrtf(vare + 1e-5f);
}

__global__ void apply_h(const float* __restrict__ g, const float* __restrict__ b)
{
    int idx = blockIdx.x * blockDim.x + threadIdx.x;
    if (idx >= Nn * Dd / 4) return;
    int d = (idx % 24) * 4;
    float4 v4 = ((const float4*)g_hnew)[idx];
    float4 h4 = ((float4*)g_h)[idx];
    h4.x += fmaxf((v4.x - g_hmu[d + 0]) * g_hrstd[d + 0] * g[d + 0] + b[d + 0], 0.f);
    h4.y += fmaxf((v4.y - g_hmu[d + 1]) * g_hrstd[d + 1] * g[d + 1] + b[d + 1], 0.f);
    h4.z += fmaxf((v4.z - g_hmu[d + 2]) * g_hrstd[d + 2] * g[d + 2] + b[d + 2], 0.f);
    h4.w += fmaxf((v4.w - g_hmu[d + 3]) * g_hrstd[d + 3] * g[d + 3] + b[d + 3], 0.f);
    ((float4*)g_h)[idx] = h4;
}

__global__ void apply_e(const float* __restrict__ g, const float* __restrict__ b)
{
    unsigned int idx = blockIdx.x * blockDim.x + threadIdx.x;   // exact: Ee*Dd/4
    int d = (idx % 24) * 4;
    float4 v4 = ((const float4*)g_enew)[idx];
    float4 e4 = ((float4*)g_e)[idx];
    e4.x += fmaxf((v4.x - g_emu[d + 0]) * g_erstd[d + 0] * g[d + 0] + b[d + 0], 0.f);
    e4.y += fmaxf((v4.y - g_emu[d + 1]) * g_erstd[d + 1] * g[d + 1] + b[d + 1], 0.f);
    e4.z += fmaxf((v4.z - g_emu[d + 2]) * g_erstd[d + 2] * g[d + 2] + b[d + 2], 0.f);
    e4.w += fmaxf((v4.w - g_emu[d + 3]) * g_erstd[d + 3] * g[d + 3] + b[d + 3], 0.f);
    ((float4*)g_e)[idx] = e4;
}

// ---------------- MLP head: relu(h@W1+b1)@W2+b2, tanh, scale ----------------
__global__ void head_kernel(const float* __restrict__ W1, const float* __restrict__ b1,
                            const float* __restrict__ W2, const float* __restrict__ b2,
                            const float* __restrict__ max_action, float* __restrict__ out)
{
    extern __shared__ float sm[];
    float* W1s = sm;                       // 96*128
    float* W2s = W1s + Dd * HID;           // 128*8
    float* hs  = W2s + HID * OUTD;         // 2*96
    float* hid = hs + 2 * Dd;              // 2*128
    int t = threadIdx.x;                   // 0..127
    int y = threadIdx.y;                   // 0..1
    int tid = y * HID + t;
    for (int i = tid; i < Dd * HID; i += 2 * HID) W1s[i] = W1[i];
    for (int i = tid; i < HID * OUTD; i += 2 * HID) W2s[i] = W2[i];
    __syncthreads();
    float* myhs = hs + y * Dd;
    float* myhid = hid + y * HID;
    int n0 = blockIdx.x * 64 + y * 32;
    for (int i = 0; i < 32; i++) {
        int n = n0 + i;
        __syncthreads();
        if (t < Dd) myhs[t] = (n < Nn) ? g_h[n * Dd + t] : 0.f;
        __syncthreads();
        float a0 = b1[t], a1 = 0.f, a2 = 0.f, a3 = 0.f;
        #pragma unroll 4
        for (int k = 0; k < Dd; k += 4) {
            a0 += myhs[k + 0] * W1s[(k + 0) * HID + t];
            a1 += myhs[k + 1] * W1s[(k + 1) * HID + t];
            a2 += myhs[k + 2] * W1s[(k + 2) * HID + t];
            a3 += myhs[k + 3] * W1s[(k + 3) * HID + t];
        }
        myhid[t] = fmaxf((a0 + a1) + (a2 + a3), 0.f);
        __syncthreads();
        if (t < OUTD && n < Nn) {
            float o0 = b2[t], o1 = 0.f;
            #pragma unroll 4
            for (int j = 0; j < HID; j += 2) {
                o0 += myhid[j + 0] * W2s[(j + 0) * OUTD + t];
                o1 += myhid[j + 1] * W2s[(j + 1) * OUTD + t];
            }
            out[n * OUTD + t] = max_action[n] * tanhf(o0 + o1);
        }
    }
}

// ---------------- launch ----------------
extern "C" void kernel_launch(void* const* d_in, const int* in_sizes, int n_in,
                              void* d_out, int out_size)
{
    const float* h1   = (const float*)d_in[0];
    const float* h2   = (const float*)d_in[1];
    const float* z    = (const float*)d_in[2];
    const float* ef   = (const float*)d_in[3];
    const float* max_action = (const float*)d_in[4];
    const float* Wh   = (const float*)d_in[5];
    const float* bh   = (const float*)d_in[6];
    const float* We   = (const float*)d_in[7];
    const float* be   = (const float*)d_in[8];
    const float* WA   = (const float*)d_in[9];
    const float* bA   = (const float*)d_in[10];
    const float* WB   = (const float*)d_in[11];
    const float* bB   = (const float*)d_in[12];
    const float* WC   = (const float*)d_in[13];
    const float* bC   = (const float*)d_in[14];
    const float* WD   = (const float*)d_in[15];
    const float* bD   = (const float*)d_in[16];
    const float* WE   = (const float*)d_in[17];
    const float* bE   = (const float*)d_in[18];
    const float* bn_h_g = (const float*)d_in[19];
    const float* bn_h_b = (const float*)d_in[20];
    const float* bn_e_g = (const float*)d_in[21];
    const float* bn_e_b = (const float*)d_in[22];
    const float* W1   = (const float*)d_in[23];
    const float* b1   = (const float*)d_in[24];
    const float* W2   = (const float*)d_in[25];
    const float* b2   = (const float*)d_in[26];
    const int*   src  = (const int*)d_in[27];
    const int*   dst  = (const int*)d_in[28];
    float* out = (float*)d_out;

    const int head_smem = (Dd * HID + HID * OUTD + 2 * Dd + 2 * HID) * (int)sizeof(float);
    cudaFuncSetAttribute(head_kernel, cudaFuncAttributeMaxDynamicSharedMemorySize, head_smem);

    float *ph, *pAh, *pBh, *pDh, *pEh;
    cudaGetSymbolAddress((void**)&ph,  g_h);
    cudaGetSymbolAddress((void**)&pAh, g_Ah);
    cudaGetSymbolAddress((void**)&pBh, g_Bh);
    cudaGetSymbolAddress((void**)&pDh, g_Dh);
    cudaGetSymbolAddress((void**)&pEh, g_Eh);

    const int node_blocks = (Nn + 63) / 64;      // 782
    dim3 blk96x4(Dd, 4);
    dim3 blkHead(HID, 2);

    embed_h<<<node_blocks, blk96x4>>>(h1, h2, z, Wh, bh);
    embed_e<<<Ee / 128, blk96x4>>>(ef, We, be);

    for (int l = 0; l < Ll; l++) {
        zero_aggr<<<(Nn * Dd) / 256, 256>>>();
        gemm96<<<node_blocks, blk96x4>>>(ph, WA + l * Dd * Dd, bA + l * Dd, pAh, Nn);
        gemm96<<<node_blocks, blk96x4>>>(ph, WB + l * Dd * Dd, bB + l * Dd, pBh, Nn);
        gemm96<<<node_blocks, blk96x4>>>(ph, WD + l * Dd * Dd, bD + l * Dd, pDh, Nn);
        gemm96<<<node_blocks, blk96x4>>>(ph, WE + l * Dd * Dd, bE + l * Dd, pEh, Nn);
        edge_fwd<<<Ee / 64, blk96x4>>>(WC + l * Dd * Dd, bC + l * Dd, src, dst);
        hnew_stats<<<node_blocks, blk96x4>>>();
        finalize_stats<<<1, Dd>>>();
        apply_h<<<(Nn * Dd / 4 + 255) / 256, 256>>>(bn_h_g + l * Dd, bn_h_b + l * Dd);
        apply_e<<<(int)(((size_t)Ee * Dd) / 4 / 256), 256>>>(bn_e_g + l * Dd, bn_e_b + l * Dd);
    }

    head_kernel<<<node_blocks, blkHead, head_smem>>>(W1, b1, W2, b2, max_action, out);
}